// round 10
// baseline (speedup 1.0000x reference)
#include <cuda_runtime.h>
#include <cuda_fp16.h>
#include <cstdint>

// ---------------- problem constants ----------------
#define NN 32768
#define DD 160     // = 10 k-steps of 16
#define FF 128
#define HH 32      // = 4 n-tiles of 8 = 2 k-steps of 16
#define KS1 10     // layer-1 k-steps
#define ROWS 128   // rows per CTA (8 warps x 1 m-tile)
#define NF 16      // networks per CTA
#define NTHR 256

#define GMT (NN / 16)              // 2048 global m-tiles
#define WBLK 12800                 // per-f weight block bytes (fp16 single W)
#define NSLOT 4                    // W ring depth

// ---------------- device scratch (no allocs) ----------------
__device__ __align__(16) uint4 g_XfragH[(size_t)GMT * KS1 * 32];   // 10.5 MB (fp16)
__device__ __align__(16) unsigned char g_Wblk[(size_t)FF * WBLK];  // 1.6 MB
// per-f block (lane-major for LDS.128):
//   W1: 10 KB @0     : uint2 index (s*32+lane)*4 + nt   (s=0..9,  lane=0..31, nt=0..3)
//   W2: 2 KB  @10240 : uint2 index (s2*32+lane)*4 + nt  (s2=0..1)
//   misc 128 floats @12288 : b1[32] | b2[32] | W3[32] | b3 @96

// ---------------- helpers ----------------
__device__ __forceinline__ uint32_t smem_u32(const void* p) {
    uint32_t a;
    asm("{ .reg .u64 t; cvta.to.shared.u64 t, %1; cvt.u32.u64 %0, t; }" : "=r"(a) : "l"(p));
    return a;
}
#define MBARRIER_INIT(addr, cnt) \
    asm volatile("mbarrier.init.shared.b64 [%0], %1;" :: "r"((uint32_t)(addr)), "r"((uint32_t)(cnt)) : "memory")
#define MBARRIER_EXPECT_TX(addr, bytes) \
    asm volatile("mbarrier.arrive.expect_tx.shared.b64 _, [%0], %1;" :: "r"((uint32_t)(addr)), "r"((uint32_t)(bytes)) : "memory")
#define MBARRIER_WAIT_PARITY(mbar_smem_addr, phase_parity) do { \
    uint32_t _mbar = (uint32_t)(mbar_smem_addr); \
    uint32_t _parity = (uint32_t)(phase_parity); \
    uint32_t _done; \
    asm volatile("{\n\t.reg .pred p;\n\t" \
        "mbarrier.try_wait.parity.acquire.cta.shared::cta.b64 p, [%1], %2;\n\t" \
        "selp.b32 %0, 1, 0, p;\n\t}" : "=r"(_done) : "r"(_mbar), "r"(_parity) : "memory"); \
    if (!_done) { \
        asm volatile("{\n\t.reg .pred P1;\n\t" \
            "WAIT_LOOP_%=:\n\t" \
            "mbarrier.try_wait.parity.acquire.cta.shared::cta.b64 P1, [%0], %1, 0x989680;\n\t" \
            "@P1 bra.uni WAIT_DONE_%=;\n\t" \
            "bra.uni WAIT_LOOP_%=;\n\t" \
            "WAIT_DONE_%=:\n\t}" :: "r"(_mbar), "r"(_parity) : "memory"); \
    } \
} while (0)
#define BULK_G2S(dst_smem, src_gmem, bytes, mbar) \
    asm volatile("cp.async.bulk.shared::cluster.global.mbarrier::complete_tx::bytes [%0], [%1], %2, [%3];" \
        :: "r"((uint32_t)(dst_smem)), "l"(src_gmem), "r"((uint32_t)(bytes)), "r"((uint32_t)(mbar)) : "memory")

// mma.m16n8k16 row.col f32.f16.f16.f32 (sm_80+ PTX; no 'a' features)
__device__ __forceinline__ void mma16816(float* c, const uint32_t* a, uint32_t b0, uint32_t b1) {
    asm volatile("mma.sync.aligned.m16n8k16.row.col.f32.f16.f16.f32 "
        "{%0,%1,%2,%3}, {%4,%5,%6,%7}, {%8,%9}, {%0,%1,%2,%3};"
        : "+f"(c[0]), "+f"(c[1]), "+f"(c[2]), "+f"(c[3])
        : "r"(a[0]), "r"(a[1]), "r"(a[2]), "r"(a[3]), "r"(b0), "r"(b1));
}

__device__ __forceinline__ float elu_f(float v) { return v > 0.0f ? v : (__expf(v) - 1.0f); }

__device__ __forceinline__ uint32_t packh2(float x, float y) {
    __half2 h = __floats2half2_rn(x, y);
    return *reinterpret_cast<uint32_t*>(&h);
}

// ---------------- merged prep: X frags (blocks 0..GMT-1) + W blocks (GMT..GMT+FF-1) ----------------
__global__ void prep_kernel(const float* __restrict__ X,
                            const float* __restrict__ W1, const float* __restrict__ W2,
                            const float* __restrict__ b1, const float* __restrict__ b2,
                            const float* __restrict__ W3, const float* __restrict__ b3) {
    if (blockIdx.x < GMT) {
        int gmt = blockIdx.x;
        int t = threadIdx.x;            // 0..319
        int s = t >> 5, lane = t & 31;
        int gid = lane >> 2, tig = lane & 3;
        int r0 = gmt * 16 + gid;
        int c0 = s * 16 + tig * 2;
        float2 v00 = *(const float2*)(X + (size_t)r0 * DD + c0);
        float2 v10 = *(const float2*)(X + (size_t)(r0 + 8) * DD + c0);
        float2 v01 = *(const float2*)(X + (size_t)r0 * DD + c0 + 8);
        float2 v11 = *(const float2*)(X + (size_t)(r0 + 8) * DD + c0 + 8);
        uint4 H;
        H.x = packh2(v00.x, v00.y);
        H.y = packh2(v10.x, v10.y);
        H.z = packh2(v01.x, v01.y);
        H.w = packh2(v11.x, v11.y);
        g_XfragH[((size_t)gmt * KS1 + s) * 32 + lane] = H;
        return;
    }
    int f = blockIdx.x - GMT;
    unsigned char* blk = g_Wblk + (size_t)f * WBLK;
    uint2* w1h = (uint2*)blk;
    uint2* w2h = (uint2*)(blk + 10240);
    float* misc = (float*)(blk + 12288);

    const float* W1f = W1 + (size_t)f * DD * HH;
    for (int i = threadIdx.x; i < KS1 * 32 * 4; i += blockDim.x) {   // 1280
        int s = i >> 7, lane = (i >> 2) & 31, nt = i & 3;
        int gid = lane >> 2, tig = lane & 3;
        int n = nt * 8 + gid, k0 = s * 16 + tig * 2;
        float w00 = W1f[k0 * HH + n],       w01 = W1f[(k0 + 1) * HH + n];
        float w10 = W1f[(k0 + 8) * HH + n], w11 = W1f[(k0 + 9) * HH + n];
        w1h[(s * 32 + lane) * 4 + nt] = make_uint2(packh2(w00, w01), packh2(w10, w11));
    }
    const float* W2f = W2 + (size_t)f * HH * HH;
    for (int i = threadIdx.x; i < 2 * 32 * 4; i += blockDim.x) {     // 256
        int s = i >> 7, lane = (i >> 2) & 31, nt = i & 3;
        int gid = lane >> 2, tig = lane & 3;
        int n = nt * 8 + gid, k0 = s * 16 + tig * 2;
        float w00 = W2f[k0 * HH + n],       w01 = W2f[(k0 + 1) * HH + n];
        float w10 = W2f[(k0 + 8) * HH + n], w11 = W2f[(k0 + 9) * HH + n];
        w2h[(s * 32 + lane) * 4 + nt] = make_uint2(packh2(w00, w01), packh2(w10, w11));
    }
    int t = threadIdx.x;
    if (t < HH)            misc[t]      = b1[f * HH + t];
    else if (t < 2 * HH)   misc[t]      = b2[f * HH + (t - HH)];
    else if (t < 3 * HH)   misc[t]      = W3[f * HH + (t - 2 * HH)];
    else if (t == 3 * HH)  misc[96]     = b3[f];
    else if (t < 128)      misc[t]      = 0.0f;
}

// ---------------- main kernel ----------------
#define SM_W    0                            // NSLOT x WBLK ring
#define SM_MB   (SM_W + NSLOT * WBLK)        // 51200
#define SMEM_DYN (SM_MB + NSLOT * 8)         // 51232

__global__ void __launch_bounds__(NTHR, 3)
mlp_main_kernel(float* __restrict__ out) {
    extern __shared__ unsigned char smem[];
    const uint32_t sb = smem_u32(smem);

    const int tile = blockIdx.x;        // 0..255  (128-row tiles)
    const int f0   = blockIdx.y * NF;   // base network
    const int tid  = threadIdx.x;
    const int wid  = tid >> 5;          // 0..7 -> m-tile within tile
    const int lane = tid & 31;
    const int gid  = lane >> 2, tig = lane & 3;

    if (tid == 0) {
        #pragma unroll
        for (int s = 0; s < NSLOT; s++) MBARRIER_INIT(sb + SM_MB + s * 8, 1);
    }
    __syncthreads();
    if (tid == 0) {
        #pragma unroll
        for (int s = 0; s < NSLOT; s++) {
            MBARRIER_EXPECT_TX(sb + SM_MB + s * 8, (uint32_t)WBLK);
            BULK_G2S(sb + SM_W + s * WBLK,
                     (const void*)(g_Wblk + (size_t)(f0 + s) * WBLK),
                     (uint32_t)WBLK, sb + SM_MB + s * 8);
        }
    }

    // ---- X fragments for this warp's m-tile: registers for all 16 f ----
    uint4 xh[KS1];
    {
        const size_t xbase = ((size_t)(tile * 8 + wid) * KS1) * 32 + lane;
        #pragma unroll
        for (int s = 0; s < KS1; s++)
            xh[s] = g_XfragH[xbase + (size_t)s * 32];
    }

    #pragma unroll 1
    for (int j = 0; j < NF; j++) {
        const int slot = j & (NSLOT - 1);
        MBARRIER_WAIT_PARITY(sb + SM_MB + slot * 8, (j >> 2) & 1);
        const unsigned char* wb = smem + SM_W + slot * WBLK;
        const float* misc = (const float*)(wb + 12288);

        // ---------- layer 1: fp16(x) @ fp16(W1) ----------
        float acc[4][4];
        #pragma unroll
        for (int nt = 0; nt < 4; nt++) {
            float bc0 = misc[nt * 8 + tig * 2];
            float bc1 = misc[nt * 8 + tig * 2 + 1];
            acc[nt][0] = bc0; acc[nt][1] = bc1;
            acc[nt][2] = bc0; acc[nt][3] = bc1;
        }
        #pragma unroll
        for (int s = 0; s < KS1; s++) {
            uint4 wA = *(const uint4*)(wb + s * 1024 + lane * 32);       // nt0, nt1
            uint4 wB = *(const uint4*)(wb + s * 1024 + lane * 32 + 16);  // nt2, nt3
            mma16816(acc[0], (const uint32_t*)&xh[s], wA.x, wA.y);
            mma16816(acc[1], (const uint32_t*)&xh[s], wA.z, wA.w);
            mma16816(acc[2], (const uint32_t*)&xh[s], wB.x, wB.y);
            mma16816(acc[3], (const uint32_t*)&xh[s], wB.z, wB.w);
        }

        // ---------- L1 epilogue: elu + fp16 -> layer-2 A frags ----------
        uint32_t a2H[2][4];
        #pragma unroll
        for (int nt = 0; nt < 4; nt++) {
            float v0 = elu_f(acc[nt][0]);
            float v1 = elu_f(acc[nt][1]);
            float v2 = elu_f(acc[nt][2]);
            float v3 = elu_f(acc[nt][3]);
            int s2 = nt >> 1, r = (nt & 1) * 2;
            a2H[s2][r + 0] = packh2(v0, v1);
            a2H[s2][r + 1] = packh2(v2, v3);
        }

        // ---------- layer 2: fp16(h1) @ fp16(W2) ----------
        float acc2[4][4];
        #pragma unroll
        for (int nt = 0; nt < 4; nt++) {
            float bc0 = misc[32 + nt * 8 + tig * 2];
            float bc1 = misc[32 + nt * 8 + tig * 2 + 1];
            acc2[nt][0] = bc0; acc2[nt][1] = bc1;
            acc2[nt][2] = bc0; acc2[nt][3] = bc1;
        }
        #pragma unroll
        for (int s2 = 0; s2 < 2; s2++) {
            uint4 wA = *(const uint4*)(wb + 10240 + s2 * 1024 + lane * 32);
            uint4 wB = *(const uint4*)(wb + 10240 + s2 * 1024 + lane * 32 + 16);
            mma16816(acc2[0], a2H[s2], wA.x, wA.y);
            mma16816(acc2[1], a2H[s2], wA.z, wA.w);
            mma16816(acc2[2], a2H[s2], wB.x, wB.y);
            mma16816(acc2[3], a2H[s2], wB.z, wB.w);
        }

        // ---------- layer 3: dot with W3 (fp32), reduce over tig quad ----------
        {
            float b3v = misc[96];
            const int f = f0 + j;
            float s0 = 0.0f, s1 = 0.0f;
            #pragma unroll
            for (int nt = 0; nt < 4; nt++) {
                float w0 = misc[64 + nt * 8 + tig * 2];
                float w1 = misc[64 + nt * 8 + tig * 2 + 1];
                s0 += elu_f(acc2[nt][0]) * w0 + elu_f(acc2[nt][1]) * w1;
                s1 += elu_f(acc2[nt][2]) * w0 + elu_f(acc2[nt][3]) * w1;
            }
            s0 += __shfl_xor_sync(0xffffffffu, s0, 1);
            s0 += __shfl_xor_sync(0xffffffffu, s0, 2);
            s1 += __shfl_xor_sync(0xffffffffu, s1, 1);
            s1 += __shfl_xor_sync(0xffffffffu, s1, 2);
            if (tig == 0) {
                int row = tile * ROWS + wid * 16 + gid;
                out[(size_t)row * FF + f]       = s0 + b3v;
                out[(size_t)(row + 8) * FF + f] = s1 + b3v;
            }
        }

        // ---- sync + refill every 2 networks (pairwise): halves barrier count ----
        if (j & 1) {
            __syncthreads();
            if (tid == 0 && j + NSLOT < NF) {
                int sA = (j - 1) & (NSLOT - 1);
                int sB = j & (NSLOT - 1);
                MBARRIER_EXPECT_TX(sb + SM_MB + sA * 8, (uint32_t)WBLK);
                BULK_G2S(sb + SM_W + sA * WBLK,
                         (const void*)(g_Wblk + (size_t)(f0 + j - 1 + NSLOT) * WBLK),
                         (uint32_t)WBLK, sb + SM_MB + sA * 8);
                MBARRIER_EXPECT_TX(sb + SM_MB + sB * 8, (uint32_t)WBLK);
                BULK_G2S(sb + SM_W + sB * WBLK,
                         (const void*)(g_Wblk + (size_t)(f0 + j + NSLOT) * WBLK),
                         (uint32_t)WBLK, sb + SM_MB + sB * 8);
            }
        }
    }
}

// ---------------- launch ----------------
extern "C" void kernel_launch(void* const* d_in, const int* in_sizes, int n_in,
                              void* d_out, int out_size) {
    const float* X  = (const float*)d_in[0];
    const float* W1 = (const float*)d_in[1];
    const float* b1 = (const float*)d_in[2];
    const float* W2 = (const float*)d_in[3];
    const float* b2 = (const float*)d_in[4];
    const float* W3 = (const float*)d_in[5];
    const float* b3 = (const float*)d_in[6];
    float* out = (float*)d_out;

    static int configured = 0;
    if (!configured) {
        cudaFuncSetAttribute(mlp_main_kernel,
                             cudaFuncAttributeMaxDynamicSharedMemorySize, SMEM_DYN);
        configured = 1;
    }

    prep_kernel<<<GMT + FF, 320>>>(X, W1, W2, b1, b2, W3, b3);
    dim3 grid(NN / ROWS, FF / NF);     // (256, 8)
    mlp_main_kernel<<<grid, NTHR, SMEM_DYN>>>(out);
}

// round 11
// speedup vs baseline: 1.3055x; 1.3055x over previous
#include <cuda_runtime.h>
#include <cuda_fp16.h>
#include <cstdint>

// ---------------- problem constants ----------------
#define NN 32768
#define DD 160     // = 10 k-steps of 16
#define FF 128
#define HH 32      // = 4 n-tiles of 8 = 2 k-steps of 16
#define KS1 10     // layer-1 k-steps
#define ROWS 128   // rows per CTA (8 warps x 1 m-tile)
#define NF 16      // networks per CTA
#define NTHR 256

#define WBLK 12800                 // per-f weight block bytes (fp16 single W)
#define NSLOT 4                    // W ring depth

// ---------------- device scratch (no allocs) ----------------
__device__ __align__(16) unsigned char g_Wblk[(size_t)FF * WBLK];  // 1.6 MB
// per-f block (R7-proven conflict-free uint2 layout):
//   W1: 10 KB @0     : uint2 index (s*4+nt)*32 + lane   (s=0..9, nt=0..3, lane=0..31)
//   W2: 2 KB  @10240 : uint2 index (s2*4+nt)*32 + lane  (s2=0..1)
//   misc 128 floats @12288 : b1[32] | b2[32] | W3[32] | b3 @96 | w3 fp16 frags @104..119

// ---------------- helpers ----------------
__device__ __forceinline__ uint32_t smem_u32(const void* p) {
    uint32_t a;
    asm("{ .reg .u64 t; cvta.to.shared.u64 t, %1; cvt.u32.u64 %0, t; }" : "=r"(a) : "l"(p));
    return a;
}
#define MBARRIER_INIT(addr, cnt) \
    asm volatile("mbarrier.init.shared.b64 [%0], %1;" :: "r"((uint32_t)(addr)), "r"((uint32_t)(cnt)) : "memory")
#define MBARRIER_EXPECT_TX(addr, bytes) \
    asm volatile("mbarrier.arrive.expect_tx.shared.b64 _, [%0], %1;" :: "r"((uint32_t)(addr)), "r"((uint32_t)(bytes)) : "memory")
#define MBARRIER_WAIT_PARITY(mbar_smem_addr, phase_parity) do { \
    uint32_t _mbar = (uint32_t)(mbar_smem_addr); \
    uint32_t _parity = (uint32_t)(phase_parity); \
    uint32_t _done; \
    asm volatile("{\n\t.reg .pred p;\n\t" \
        "mbarrier.try_wait.parity.acquire.cta.shared::cta.b64 p, [%1], %2;\n\t" \
        "selp.b32 %0, 1, 0, p;\n\t}" : "=r"(_done) : "r"(_mbar), "r"(_parity) : "memory"); \
    if (!_done) { \
        asm volatile("{\n\t.reg .pred P1;\n\t" \
            "WAIT_LOOP_%=:\n\t" \
            "mbarrier.try_wait.parity.acquire.cta.shared::cta.b64 P1, [%0], %1, 0x989680;\n\t" \
            "@P1 bra.uni WAIT_DONE_%=;\n\t" \
            "bra.uni WAIT_LOOP_%=;\n\t" \
            "WAIT_DONE_%=:\n\t}" :: "r"(_mbar), "r"(_parity) : "memory"); \
    } \
} while (0)
#define BULK_G2S(dst_smem, src_gmem, bytes, mbar) \
    asm volatile("cp.async.bulk.shared::cluster.global.mbarrier::complete_tx::bytes [%0], [%1], %2, [%3];" \
        :: "r"((uint32_t)(dst_smem)), "l"(src_gmem), "r"((uint32_t)(bytes)), "r"((uint32_t)(mbar)) : "memory")

// mma.m16n8k16 row.col f32.f16.f16.f32 (sm_80+ PTX; no 'a' features)
__device__ __forceinline__ void mma16816(float* c, const uint32_t* a, uint32_t b0, uint32_t b1) {
    asm volatile("mma.sync.aligned.m16n8k16.row.col.f32.f16.f16.f32 "
        "{%0,%1,%2,%3}, {%4,%5,%6,%7}, {%8,%9}, {%0,%1,%2,%3};"
        : "+f"(c[0]), "+f"(c[1]), "+f"(c[2]), "+f"(c[3])
        : "r"(a[0]), "r"(a[1]), "r"(a[2]), "r"(a[3]), "r"(b0), "r"(b1));
}

__device__ __forceinline__ float elu_f(float v) { return v > 0.0f ? v : (__expf(v) - 1.0f); }

__device__ __forceinline__ uint32_t packh2(float x, float y) {
    __half2 h = __floats2half2_rn(x, y);
    return *reinterpret_cast<uint32_t*>(&h);
}

// ---------------- prep: W -> B-fragment order (fp16) + misc (incl. fp16 W3 frags) ----------------
__global__ void prep_w_kernel(const float* __restrict__ W1, const float* __restrict__ W2,
                              const float* __restrict__ b1, const float* __restrict__ b2,
                              const float* __restrict__ W3, const float* __restrict__ b3) {
    int f = blockIdx.x;
    unsigned char* blk = g_Wblk + (size_t)f * WBLK;
    uint2* w1h = (uint2*)blk;
    uint2* w2h = (uint2*)(blk + 10240);
    float* misc = (float*)(blk + 12288);

    const float* W1f = W1 + (size_t)f * DD * HH;
    for (int i = threadIdx.x; i < KS1 * 4 * 32; i += blockDim.x) {   // 1280, idx = (s*4+nt)*32+lane
        int s = i >> 7, nt = (i >> 5) & 3, lane = i & 31;
        int gid = lane >> 2, tig = lane & 3;
        int n = nt * 8 + gid, k0 = s * 16 + tig * 2;
        float w00 = W1f[k0 * HH + n],       w01 = W1f[(k0 + 1) * HH + n];
        float w10 = W1f[(k0 + 8) * HH + n], w11 = W1f[(k0 + 9) * HH + n];
        w1h[i] = make_uint2(packh2(w00, w01), packh2(w10, w11));
    }
    const float* W2f = W2 + (size_t)f * HH * HH;
    for (int i = threadIdx.x; i < 2 * 4 * 32; i += blockDim.x) {     // 256
        int s = i >> 7, nt = (i >> 5) & 3, lane = i & 31;
        int gid = lane >> 2, tig = lane & 3;
        int n = nt * 8 + gid, k0 = s * 16 + tig * 2;
        float w00 = W2f[k0 * HH + n],       w01 = W2f[(k0 + 1) * HH + n];
        float w10 = W2f[(k0 + 8) * HH + n], w11 = W2f[(k0 + 9) * HH + n];
        w2h[i] = make_uint2(packh2(w00, w01), packh2(w10, w11));
    }
    const float* W3f = W3 + (size_t)f * HH;
    int t = threadIdx.x;
    if (t < HH)            misc[t]      = b1[f * HH + t];
    else if (t < 2 * HH)   misc[t]      = b2[f * HH + (t - HH)];
    else if (t < 3 * HH)   misc[t]      = W3f[t - 2 * HH];
    else if (t == 3 * HH)  misc[96]     = b3[f];
    else if (t >= 104 && t < 120) {
        // fp16 W3 B-fragments, replicated over n: idx = (s3*4+tig)*2 + jj
        int k = t - 104;
        int jj = k & 1, tg = (k >> 1) & 3, s3 = k >> 3;
        int kk = s3 * 16 + jj * 8 + tg * 2;
        ((uint32_t*)misc)[t] = packh2(W3f[kk], W3f[kk + 1]);
    }
    else if (t < 128)      misc[t]      = 0.0f;
}

// ---------------- main kernel ----------------
#define SM_W    0                            // NSLOT x WBLK ring
#define SM_MB   (SM_W + NSLOT * WBLK)        // 51200
#define SMEM_DYN (SM_MB + NSLOT * 8)         // 51232

__global__ void __launch_bounds__(NTHR, 3)
mlp_main_kernel(const float* __restrict__ X, float* __restrict__ out) {
    extern __shared__ unsigned char smem[];
    const uint32_t sb = smem_u32(smem);

    const int tile = blockIdx.x;        // 0..255  (128-row tiles)
    const int f0   = blockIdx.y * NF;   // base network
    const int tid  = threadIdx.x;
    const int wid  = tid >> 5;          // 0..7 -> m-tile within tile
    const int lane = tid & 31;
    const int gid  = lane >> 2, tig = lane & 3;

    if (tid == 0) {
        #pragma unroll
        for (int s = 0; s < NSLOT; s++) MBARRIER_INIT(sb + SM_MB + s * 8, 1);
    }
    __syncthreads();
    if (tid == 0) {
        #pragma unroll
        for (int s = 0; s < NSLOT; s++) {
            MBARRIER_EXPECT_TX(sb + SM_MB + s * 8, (uint32_t)WBLK);
            BULK_G2S(sb + SM_W + s * WBLK,
                     (const void*)(g_Wblk + (size_t)(f0 + s) * WBLK),
                     (uint32_t)WBLK, sb + SM_MB + s * 8);
        }
    }

    // ---- X A-fragments built directly from gmem (no prep_x, no scratch round-trip) ----
    uint4 xh[KS1];
    {
        const int row0 = tile * ROWS + wid * 16 + gid;
        const float* xr0 = X + (size_t)row0 * DD;
        const float* xr8 = X + (size_t)(row0 + 8) * DD;
        #pragma unroll
        for (int s = 0; s < KS1; s++) {
            int c0 = s * 16 + tig * 2;
            float2 v00 = *(const float2*)(xr0 + c0);
            float2 v10 = *(const float2*)(xr8 + c0);
            float2 v01 = *(const float2*)(xr0 + c0 + 8);
            float2 v11 = *(const float2*)(xr8 + c0 + 8);
            xh[s].x = packh2(v00.x, v00.y);
            xh[s].y = packh2(v10.x, v10.y);
            xh[s].z = packh2(v01.x, v01.y);
            xh[s].w = packh2(v11.x, v11.y);
        }
    }

    #pragma unroll 1
    for (int j = 0; j < NF; j++) {
        const int slot = j & (NSLOT - 1);
        MBARRIER_WAIT_PARITY(sb + SM_MB + slot * 8, (j >> 2) & 1);
        const unsigned char* wb = smem + SM_W + slot * WBLK;
        const uint2* W1H = (const uint2*)wb;
        const uint2* W2H = (const uint2*)(wb + 10240);
        const float* misc = (const float*)(wb + 12288);

        // ---------- layer 1: fp16(x) @ fp16(W1) ----------
        float acc[4][4];
        #pragma unroll
        for (int nt = 0; nt < 4; nt++) {
            float bc0 = misc[nt * 8 + tig * 2];
            float bc1 = misc[nt * 8 + tig * 2 + 1];
            acc[nt][0] = bc0; acc[nt][1] = bc1;
            acc[nt][2] = bc0; acc[nt][3] = bc1;
        }
        #pragma unroll
        for (int s = 0; s < KS1; s++) {
            uint2 bh0 = W1H[(s * 4 + 0) * 32 + lane];
            uint2 bh1 = W1H[(s * 4 + 1) * 32 + lane];
            uint2 bh2 = W1H[(s * 4 + 2) * 32 + lane];
            uint2 bh3 = W1H[(s * 4 + 3) * 32 + lane];
            mma16816(acc[0], (const uint32_t*)&xh[s], bh0.x, bh0.y);
            mma16816(acc[1], (const uint32_t*)&xh[s], bh1.x, bh1.y);
            mma16816(acc[2], (const uint32_t*)&xh[s], bh2.x, bh2.y);
            mma16816(acc[3], (const uint32_t*)&xh[s], bh3.x, bh3.y);
        }

        // ---------- L1 epilogue: elu + fp16 -> layer-2 A frags ----------
        uint32_t a2H[2][4];
        #pragma unroll
        for (int nt = 0; nt < 4; nt++) {
            float v0 = elu_f(acc[nt][0]);
            float v1 = elu_f(acc[nt][1]);
            float v2 = elu_f(acc[nt][2]);
            float v3 = elu_f(acc[nt][3]);
            int s2 = nt >> 1, r = (nt & 1) * 2;
            a2H[s2][r + 0] = packh2(v0, v1);
            a2H[s2][r + 1] = packh2(v2, v3);
        }

        // ---------- layer 2: fp16(h1) @ fp16(W2) ----------
        float acc2[4][4];
        #pragma unroll
        for (int nt = 0; nt < 4; nt++) {
            float bc0 = misc[32 + nt * 8 + tig * 2];
            float bc1 = misc[32 + nt * 8 + tig * 2 + 1];
            acc2[nt][0] = bc0; acc2[nt][1] = bc1;
            acc2[nt][2] = bc0; acc2[nt][3] = bc1;
        }
        #pragma unroll
        for (int s2 = 0; s2 < 2; s2++) {
            uint2 bh0 = W2H[(s2 * 4 + 0) * 32 + lane];
            uint2 bh1 = W2H[(s2 * 4 + 1) * 32 + lane];
            uint2 bh2 = W2H[(s2 * 4 + 2) * 32 + lane];
            uint2 bh3 = W2H[(s2 * 4 + 3) * 32 + lane];
            mma16816(acc2[0], a2H[s2], bh0.x, bh0.y);
            mma16816(acc2[1], a2H[s2], bh1.x, bh1.y);
            mma16816(acc2[2], a2H[s2], bh2.x, bh2.y);
            mma16816(acc2[3], a2H[s2], bh3.x, bh3.y);
        }

        // ---------- layer 3 as 2 MMAs: elu(h2) packed as A frags; W3 fp16 frags
        //            replicated over N so every output column = the dot; C init = b3 ----------
        {
            const uint2* w3f = (const uint2*)(misc + 104);   // idx s3*4 + tig
            uint32_t a3H[2][4];
            #pragma unroll
            for (int nt = 0; nt < 4; nt++) {
                float v0 = elu_f(acc2[nt][0]);
                float v1 = elu_f(acc2[nt][1]);
                float v2 = elu_f(acc2[nt][2]);
                float v3 = elu_f(acc2[nt][3]);
                int s3 = nt >> 1, r = (nt & 1) * 2;
                a3H[s3][r + 0] = packh2(v0, v1);
                a3H[s3][r + 1] = packh2(v2, v3);
            }
            float b3v = misc[96];
            float c3[4] = {b3v, b3v, b3v, b3v};
            uint2 w0 = w3f[tig];
            uint2 w1 = w3f[4 + tig];
            mma16816(c3, a3H[0], w0.x, w0.y);
            mma16816(c3, a3H[1], w1.x, w1.y);
            if (tig == 0) {
                const int f = f0 + j;
                int row = tile * ROWS + wid * 16 + gid;
                out[(size_t)row * FF + f]       = c3[0];
                out[(size_t)(row + 8) * FF + f] = c3[2];
            }
        }

        __syncthreads();   // all warps done with this W slot
        if (tid == 0 && j + NSLOT < NF) {
            uint32_t mb = sb + SM_MB + slot * 8;
            MBARRIER_EXPECT_TX(mb, (uint32_t)WBLK);
            BULK_G2S(sb + SM_W + slot * WBLK,
                     (const void*)(g_Wblk + (size_t)(f0 + j + NSLOT) * WBLK),
                     (uint32_t)WBLK, mb);
        }
    }
}

// ---------------- launch ----------------
extern "C" void kernel_launch(void* const* d_in, const int* in_sizes, int n_in,
                              void* d_out, int out_size) {
    const float* X  = (const float*)d_in[0];
    const float* W1 = (const float*)d_in[1];
    const float* b1 = (const float*)d_in[2];
    const float* W2 = (const float*)d_in[3];
    const float* b2 = (const float*)d_in[4];
    const float* W3 = (const float*)d_in[5];
    const float* b3 = (const float*)d_in[6];
    float* out = (float*)d_out;

    static int configured = 0;
    if (!configured) {
        cudaFuncSetAttribute(mlp_main_kernel,
                             cudaFuncAttributeMaxDynamicSharedMemorySize, SMEM_DYN);
        configured = 1;
    }

    prep_w_kernel<<<FF, 256>>>(W1, W2, b1, b2, W3, b3);
    dim3 grid(NN / ROWS, FF / NF);     // (256, 8)
    mlp_main_kernel<<<grid, NTHR, SMEM_DYN>>>(X, out);
}

// round 12
// speedup vs baseline: 1.3527x; 1.0362x over previous
#include <cuda_runtime.h>
#include <cuda_fp16.h>
#include <cstdint>

// ---------------- problem constants ----------------
#define NN 32768
#define DD 160     // = 10 k-steps of 16
#define FF 128
#define HH 32      // = 4 n-tiles of 8 = 2 k-steps of 16
#define KS1 10     // layer-1 k-steps
#define ROWS 128   // rows per CTA (8 warps x 1 m-tile)
#define NF 8       // networks per CTA (shorter CTAs -> better tail packing)
#define NTHR 256

#define GMT (NN / 16)              // 2048 global m-tiles
#define WBLK 12800                 // per-f weight block bytes (fp16 single W)
#define NSLOT 4                    // W ring depth

// ---------------- device scratch (no allocs) ----------------
__device__ __align__(16) uint4 g_XfragH[(size_t)GMT * KS1 * 32];   // 10.5 MB (fp16)
__device__ __align__(16) unsigned char g_Wblk[(size_t)FF * WBLK];  // 1.6 MB
// per-f block (R7-proven conflict-free uint2 layout):
//   W1: 10 KB @0     : uint2 index (s*4+nt)*32 + lane   (s=0..9, nt=0..3, lane=0..31)
//   W2: 2 KB  @10240 : uint2 index (s2*4+nt)*32 + lane  (s2=0..1)
//   misc 128 words @12288 : b1[32] | b2[32] | W3[32] | b3 @96 | w3 fp16 frags @104..119

// ---------------- helpers ----------------
__device__ __forceinline__ uint32_t smem_u32(const void* p) {
    uint32_t a;
    asm("{ .reg .u64 t; cvta.to.shared.u64 t, %1; cvt.u32.u64 %0, t; }" : "=r"(a) : "l"(p));
    return a;
}
#define MBARRIER_INIT(addr, cnt) \
    asm volatile("mbarrier.init.shared.b64 [%0], %1;" :: "r"((uint32_t)(addr)), "r"((uint32_t)(cnt)) : "memory")
#define MBARRIER_EXPECT_TX(addr, bytes) \
    asm volatile("mbarrier.arrive.expect_tx.shared.b64 _, [%0], %1;" :: "r"((uint32_t)(addr)), "r"((uint32_t)(bytes)) : "memory")
#define MBARRIER_WAIT_PARITY(mbar_smem_addr, phase_parity) do { \
    uint32_t _mbar = (uint32_t)(mbar_smem_addr); \
    uint32_t _parity = (uint32_t)(phase_parity); \
    uint32_t _done; \
    asm volatile("{\n\t.reg .pred p;\n\t" \
        "mbarrier.try_wait.parity.acquire.cta.shared::cta.b64 p, [%1], %2;\n\t" \
        "selp.b32 %0, 1, 0, p;\n\t}" : "=r"(_done) : "r"(_mbar), "r"(_parity) : "memory"); \
    if (!_done) { \
        asm volatile("{\n\t.reg .pred P1;\n\t" \
            "WAIT_LOOP_%=:\n\t" \
            "mbarrier.try_wait.parity.acquire.cta.shared::cta.b64 P1, [%0], %1, 0x989680;\n\t" \
            "@P1 bra.uni WAIT_DONE_%=;\n\t" \
            "bra.uni WAIT_LOOP_%=;\n\t" \
            "WAIT_DONE_%=:\n\t}" :: "r"(_mbar), "r"(_parity) : "memory"); \
    } \
} while (0)
#define BULK_G2S(dst_smem, src_gmem, bytes, mbar) \
    asm volatile("cp.async.bulk.shared::cluster.global.mbarrier::complete_tx::bytes [%0], [%1], %2, [%3];" \
        :: "r"((uint32_t)(dst_smem)), "l"(src_gmem), "r"((uint32_t)(bytes)), "r"((uint32_t)(mbar)) : "memory")

// mma.m16n8k16 row.col f32.f16.f16.f32 (sm_80+ PTX; no 'a' features)
__device__ __forceinline__ void mma16816(float* c, const uint32_t* a, uint32_t b0, uint32_t b1) {
    asm volatile("mma.sync.aligned.m16n8k16.row.col.f32.f16.f16.f32 "
        "{%0,%1,%2,%3}, {%4,%5,%6,%7}, {%8,%9}, {%0,%1,%2,%3};"
        : "+f"(c[0]), "+f"(c[1]), "+f"(c[2]), "+f"(c[3])
        : "r"(a[0]), "r"(a[1]), "r"(a[2]), "r"(a[3]), "r"(b0), "r"(b1));
}

__device__ __forceinline__ float elu_f(float v) { return v > 0.0f ? v : (__expf(v) - 1.0f); }

__device__ __forceinline__ uint32_t packh2(float x, float y) {
    __half2 h = __floats2half2_rn(x, y);
    return *reinterpret_cast<uint32_t*>(&h);
}

// ---------------- merged prep: X frags (blocks 0..GMT-1) + W blocks (GMT..GMT+FF-1) ----------------
__global__ void prep_kernel(const float* __restrict__ X,
                            const float* __restrict__ W1, const float* __restrict__ W2,
                            const float* __restrict__ b1, const float* __restrict__ b2,
                            const float* __restrict__ W3, const float* __restrict__ b3) {
    if (blockIdx.x < GMT) {
        int gmt = blockIdx.x;
        int t = threadIdx.x;            // 0..319
        int s = t >> 5, lane = t & 31;
        int gid = lane >> 2, tig = lane & 3;
        int r0 = gmt * 16 + gid;
        int c0 = s * 16 + tig * 2;
        float2 v00 = *(const float2*)(X + (size_t)r0 * DD + c0);
        float2 v10 = *(const float2*)(X + (size_t)(r0 + 8) * DD + c0);
        float2 v01 = *(const float2*)(X + (size_t)r0 * DD + c0 + 8);
        float2 v11 = *(const float2*)(X + (size_t)(r0 + 8) * DD + c0 + 8);
        uint4 H;
        H.x = packh2(v00.x, v00.y);
        H.y = packh2(v10.x, v10.y);
        H.z = packh2(v01.x, v01.y);
        H.w = packh2(v11.x, v11.y);
        g_XfragH[((size_t)gmt * KS1 + s) * 32 + lane] = H;
        return;
    }
    int f = blockIdx.x - GMT;
    unsigned char* blk = g_Wblk + (size_t)f * WBLK;
    uint2* w1h = (uint2*)blk;
    uint2* w2h = (uint2*)(blk + 10240);
    float* misc = (float*)(blk + 12288);

    const float* W1f = W1 + (size_t)f * DD * HH;
    for (int i = threadIdx.x; i < KS1 * 4 * 32; i += blockDim.x) {   // 1280, idx = (s*4+nt)*32+lane
        int s = i >> 7, nt = (i >> 5) & 3, lane = i & 31;
        int gid = lane >> 2, tig = lane & 3;
        int n = nt * 8 + gid, k0 = s * 16 + tig * 2;
        float w00 = W1f[k0 * HH + n],       w01 = W1f[(k0 + 1) * HH + n];
        float w10 = W1f[(k0 + 8) * HH + n], w11 = W1f[(k0 + 9) * HH + n];
        w1h[i] = make_uint2(packh2(w00, w01), packh2(w10, w11));
    }
    const float* W2f = W2 + (size_t)f * HH * HH;
    for (int i = threadIdx.x; i < 2 * 4 * 32; i += blockDim.x) {     // 256
        int s = i >> 7, nt = (i >> 5) & 3, lane = i & 31;
        int gid = lane >> 2, tig = lane & 3;
        int n = nt * 8 + gid, k0 = s * 16 + tig * 2;
        float w00 = W2f[k0 * HH + n],       w01 = W2f[(k0 + 1) * HH + n];
        float w10 = W2f[(k0 + 8) * HH + n], w11 = W2f[(k0 + 9) * HH + n];
        w2h[i] = make_uint2(packh2(w00, w01), packh2(w10, w11));
    }
    const float* W3f = W3 + (size_t)f * HH;
    int t = threadIdx.x;
    if (t < HH)            misc[t]      = b1[f * HH + t];
    else if (t < 2 * HH)   misc[t]      = b2[f * HH + (t - HH)];
    else if (t < 3 * HH)   misc[t]      = W3f[t - 2 * HH];
    else if (t == 3 * HH)  misc[96]     = b3[f];
    else if (t >= 104 && t < 120) {
        // fp16 W3 B-fragments, replicated over n: idx = (s3*4+tig)*2 + jj
        int k = t - 104;
        int jj = k & 1, tg = (k >> 1) & 3, s3 = k >> 3;
        int kk = s3 * 16 + jj * 8 + tg * 2;
        ((uint32_t*)misc)[t] = packh2(W3f[kk], W3f[kk + 1]);
    }
    else if (t < 128 && t >= 97) misc[t] = 0.0f;
}

// ---------------- main kernel ----------------
#define SM_W    0                            // NSLOT x WBLK ring
#define SM_MB   (SM_W + NSLOT * WBLK)        // 51200
#define SMEM_DYN (SM_MB + NSLOT * 8)         // 51232

__global__ void __launch_bounds__(NTHR, 3)
mlp_main_kernel(float* __restrict__ out) {
    extern __shared__ unsigned char smem[];
    const uint32_t sb = smem_u32(smem);

    const int tile = blockIdx.x;        // 0..255  (128-row tiles)
    const int f0   = blockIdx.y * NF;   // base network
    const int tid  = threadIdx.x;
    const int wid  = tid >> 5;          // 0..7 -> m-tile within tile
    const int lane = tid & 31;
    const int gid  = lane >> 2, tig = lane & 3;

    if (tid == 0) {
        #pragma unroll
        for (int s = 0; s < NSLOT; s++) MBARRIER_INIT(sb + SM_MB + s * 8, 1);
    }
    __syncthreads();
    if (tid == 0) {
        #pragma unroll
        for (int s = 0; s < NSLOT; s++) {
            MBARRIER_EXPECT_TX(sb + SM_MB + s * 8, (uint32_t)WBLK);
            BULK_G2S(sb + SM_W + s * WBLK,
                     (const void*)(g_Wblk + (size_t)(f0 + s) * WBLK),
                     (uint32_t)WBLK, sb + SM_MB + s * 8);
        }
    }

    // ---- X fragments for this warp's m-tile: registers for all NF f ----
    uint4 xh[KS1];
    {
        const size_t xbase = ((size_t)(tile * 8 + wid) * KS1) * 32 + lane;
        #pragma unroll
        for (int s = 0; s < KS1; s++)
            xh[s] = g_XfragH[xbase + (size_t)s * 32];
    }

    #pragma unroll 1
    for (int j = 0; j < NF; j++) {
        const int slot = j & (NSLOT - 1);
        MBARRIER_WAIT_PARITY(sb + SM_MB + slot * 8, (j >> 2) & 1);
        const unsigned char* wb = smem + SM_W + slot * WBLK;
        const uint2* W1H = (const uint2*)wb;
        const uint2* W2H = (const uint2*)(wb + 10240);
        const float* misc = (const float*)(wb + 12288);

        // ---------- layer 1: fp16(x) @ fp16(W1) ----------
        float acc[4][4];
        #pragma unroll
        for (int nt = 0; nt < 4; nt++) {
            float bc0 = misc[nt * 8 + tig * 2];
            float bc1 = misc[nt * 8 + tig * 2 + 1];
            acc[nt][0] = bc0; acc[nt][1] = bc1;
            acc[nt][2] = bc0; acc[nt][3] = bc1;
        }
        #pragma unroll
        for (int s = 0; s < KS1; s++) {
            uint2 bh0 = W1H[(s * 4 + 0) * 32 + lane];
            uint2 bh1 = W1H[(s * 4 + 1) * 32 + lane];
            uint2 bh2 = W1H[(s * 4 + 2) * 32 + lane];
            uint2 bh3 = W1H[(s * 4 + 3) * 32 + lane];
            mma16816(acc[0], (const uint32_t*)&xh[s], bh0.x, bh0.y);
            mma16816(acc[1], (const uint32_t*)&xh[s], bh1.x, bh1.y);
            mma16816(acc[2], (const uint32_t*)&xh[s], bh2.x, bh2.y);
            mma16816(acc[3], (const uint32_t*)&xh[s], bh3.x, bh3.y);
        }

        // ---------- L1 epilogue: elu + fp16 -> layer-2 A frags ----------
        uint32_t a2H[2][4];
        #pragma unroll
        for (int nt = 0; nt < 4; nt++) {
            float v0 = elu_f(acc[nt][0]);
            float v1 = elu_f(acc[nt][1]);
            float v2 = elu_f(acc[nt][2]);
            float v3 = elu_f(acc[nt][3]);
            int s2 = nt >> 1, r = (nt & 1) * 2;
            a2H[s2][r + 0] = packh2(v0, v1);
            a2H[s2][r + 1] = packh2(v2, v3);
        }

        // ---------- layer 2: fp16(h1) @ fp16(W2) ----------
        float acc2[4][4];
        #pragma unroll
        for (int nt = 0; nt < 4; nt++) {
            float bc0 = misc[32 + nt * 8 + tig * 2];
            float bc1 = misc[32 + nt * 8 + tig * 2 + 1];
            acc2[nt][0] = bc0; acc2[nt][1] = bc1;
            acc2[nt][2] = bc0; acc2[nt][3] = bc1;
        }
        #pragma unroll
        for (int s2 = 0; s2 < 2; s2++) {
            uint2 bh0 = W2H[(s2 * 4 + 0) * 32 + lane];
            uint2 bh1 = W2H[(s2 * 4 + 1) * 32 + lane];
            uint2 bh2 = W2H[(s2 * 4 + 2) * 32 + lane];
            uint2 bh3 = W2H[(s2 * 4 + 3) * 32 + lane];
            mma16816(acc2[0], a2H[s2], bh0.x, bh0.y);
            mma16816(acc2[1], a2H[s2], bh1.x, bh1.y);
            mma16816(acc2[2], a2H[s2], bh2.x, bh2.y);
            mma16816(acc2[3], a2H[s2], bh3.x, bh3.y);
        }

        // ---------- layer 3 as 2 MMAs: elu(h2) packed as A frags; W3 fp16 frags
        //            replicated over N (every output col = the dot); C init = b3 ----------
        {
            const uint2* w3f = (const uint2*)(misc + 104);   // idx s3*4 + tig
            uint32_t a3H[2][4];
            #pragma unroll
            for (int nt = 0; nt < 4; nt++) {
                float v0 = elu_f(acc2[nt][0]);
                float v1 = elu_f(acc2[nt][1]);
                float v2 = elu_f(acc2[nt][2]);
                float v3 = elu_f(acc2[nt][3]);
                int s3 = nt >> 1, r = (nt & 1) * 2;
                a3H[s3][r + 0] = packh2(v0, v1);
                a3H[s3][r + 1] = packh2(v2, v3);
            }
            float b3v = misc[96];
            float c3[4] = {b3v, b3v, b3v, b3v};
            uint2 w0 = w3f[tig];
            uint2 w1 = w3f[4 + tig];
            mma16816(c3, a3H[0], w0.x, w0.y);
            mma16816(c3, a3H[1], w1.x, w1.y);
            if (tig == 0) {
                const int f = f0 + j;
                int row = tile * ROWS + wid * 16 + gid;
                out[(size_t)row * FF + f]       = c3[0];
                out[(size_t)(row + 8) * FF + f] = c3[2];
            }
        }

        __syncthreads();   // all warps done with this W slot
        if (tid == 0 && j + NSLOT < NF) {
            uint32_t mb = sb + SM_MB + slot * 8;
            MBARRIER_EXPECT_TX(mb, (uint32_t)WBLK);
            BULK_G2S(sb + SM_W + slot * WBLK,
                     (const void*)(g_Wblk + (size_t)(f0 + j + NSLOT) * WBLK),
                     (uint32_t)WBLK, mb);
        }
    }
}

// ---------------- launch ----------------
extern "C" void kernel_launch(void* const* d_in, const int* in_sizes, int n_in,
                              void* d_out, int out_size) {
    const float* X  = (const float*)d_in[0];
    const float* W1 = (const float*)d_in[1];
    const float* b1 = (const float*)d_in[2];
    const float* W2 = (const float*)d_in[3];
    const float* b2 = (const float*)d_in[4];
    const float* W3 = (const float*)d_in[5];
    const float* b3 = (const float*)d_in[6];
    float* out = (float*)d_out;

    static int configured = 0;
    if (!configured) {
        cudaFuncSetAttribute(mlp_main_kernel,
                             cudaFuncAttributeMaxDynamicSharedMemorySize, SMEM_DYN);
        configured = 1;
    }

    prep_kernel<<<GMT + FF, 320>>>(X, W1, W2, b1, b2, W3, b3);
    dim3 grid(NN / ROWS, FF / NF);     // (256, 16)
    mlp_main_kernel<<<grid, NTHR, SMEM_DYN>>>(out);
}

// round 13
// speedup vs baseline: 1.6773x; 1.2399x over previous
#include <cuda_runtime.h>
#include <cuda_fp16.h>
#include <cstdint>

// ---------------- problem constants ----------------
#define NN 32768
#define DD 160     // = 10 k-steps of 16
#define FF 128
#define HH 32      // = 4 n-tiles of 8 = 2 k-steps of 16
#define KS1 10     // layer-1 k-steps
#define ROWS 128   // rows per CTA (8 warps x 1 m-tile)
#define NF 16      // networks per CTA
#define NTHR 256

#define GMT (NN / 16)              // 2048 global m-tiles
#define WBLK 12800                 // per-f weight block bytes (fp16 single W)
#define NSLOT 4                    // W ring depth

// ---------------- device scratch (no allocs) ----------------
__device__ __align__(16) uint4 g_XfragH[(size_t)GMT * KS1 * 32];   // 10.5 MB (fp16)
__device__ __align__(16) unsigned char g_Wblk[(size_t)FF * WBLK];  // 1.6 MB
// per-f block (R7-proven conflict-free uint2 layout):
//   W1: 10 KB @0     : uint2 index (s*4+nt)*32 + lane   (s=0..9, nt=0..3, lane=0..31)
//   W2: 2 KB  @10240 : uint2 index (s2*4+nt)*32 + lane  (s2=0..1)
//   misc 128 words @12288 : b1[32] | b2[32] | W3[32] | b3 @96 | w3 fp16 frags @104..119

// ---------------- helpers ----------------
__device__ __forceinline__ uint32_t smem_u32(const void* p) {
    uint32_t a;
    asm("{ .reg .u64 t; cvta.to.shared.u64 t, %1; cvt.u32.u64 %0, t; }" : "=r"(a) : "l"(p));
    return a;
}
#define MBARRIER_INIT(addr, cnt) \
    asm volatile("mbarrier.init.shared.b64 [%0], %1;" :: "r"((uint32_t)(addr)), "r"((uint32_t)(cnt)) : "memory")
#define MBARRIER_EXPECT_TX(addr, bytes) \
    asm volatile("mbarrier.arrive.expect_tx.shared.b64 _, [%0], %1;" :: "r"((uint32_t)(addr)), "r"((uint32_t)(bytes)) : "memory")
#define MBARRIER_WAIT_PARITY(mbar_smem_addr, phase_parity) do { \
    uint32_t _mbar = (uint32_t)(mbar_smem_addr); \
    uint32_t _parity = (uint32_t)(phase_parity); \
    uint32_t _done; \
    asm volatile("{\n\t.reg .pred p;\n\t" \
        "mbarrier.try_wait.parity.acquire.cta.shared::cta.b64 p, [%1], %2;\n\t" \
        "selp.b32 %0, 1, 0, p;\n\t}" : "=r"(_done) : "r"(_mbar), "r"(_parity) : "memory"); \
    if (!_done) { \
        asm volatile("{\n\t.reg .pred P1;\n\t" \
            "WAIT_LOOP_%=:\n\t" \
            "mbarrier.try_wait.parity.acquire.cta.shared::cta.b64 P1, [%0], %1, 0x989680;\n\t" \
            "@P1 bra.uni WAIT_DONE_%=;\n\t" \
            "bra.uni WAIT_LOOP_%=;\n\t" \
            "WAIT_DONE_%=:\n\t}" :: "r"(_mbar), "r"(_parity) : "memory"); \
    } \
} while (0)
#define BULK_G2S(dst_smem, src_gmem, bytes, mbar) \
    asm volatile("cp.async.bulk.shared::cluster.global.mbarrier::complete_tx::bytes [%0], [%1], %2, [%3];" \
        :: "r"((uint32_t)(dst_smem)), "l"(src_gmem), "r"((uint32_t)(bytes)), "r"((uint32_t)(mbar)) : "memory")

// mma.m16n8k16 row.col f32.f16.f16.f32 (sm_80+ PTX; no 'a' features)
__device__ __forceinline__ void mma16816(float* c, const uint32_t* a, uint32_t b0, uint32_t b1) {
    asm volatile("mma.sync.aligned.m16n8k16.row.col.f32.f16.f16.f32 "
        "{%0,%1,%2,%3}, {%4,%5,%6,%7}, {%8,%9}, {%0,%1,%2,%3};"
        : "+f"(c[0]), "+f"(c[1]), "+f"(c[2]), "+f"(c[3])
        : "r"(a[0]), "r"(a[1]), "r"(a[2]), "r"(a[3]), "r"(b0), "r"(b1));
}

__device__ __forceinline__ float elu_f(float v) { return v > 0.0f ? v : (__expf(v) - 1.0f); }

__device__ __forceinline__ uint32_t packh2(float x, float y) {
    __half2 h = __floats2half2_rn(x, y);
    return *reinterpret_cast<uint32_t*>(&h);
}

// Packed fp16 elu of a pair of fp32 accumulators:
//   elu(x) = max(x,0) + (exp(min(x,0)) - 1), exp via ex2.approx.f16x2.
//   Positives stay exact: e-1 = 0 exactly; mx + 0 = mx.
__device__ __forceinline__ uint32_t elu2(float x, float y) {
    __half2 h = __floats2half2_rn(x, y);
    const __half2 z   = __floats2half2_rn(0.0f, 0.0f);
    const __half2 l2e = __floats2half2_rn(1.4426950408889634f, 1.4426950408889634f);
    const __half2 m1  = __floats2half2_rn(-1.0f, -1.0f);
    __half2 mn = __hmin2(h, z);
    __half2 mx = __hmax2(h, z);
    __half2 t  = __hmul2(mn, l2e);
    uint32_t tu = *reinterpret_cast<uint32_t*>(&t);
    uint32_t eu;
    asm("ex2.approx.f16x2 %0, %1;" : "=r"(eu) : "r"(tu));
    __half2 e = *reinterpret_cast<__half2*>(&eu);
    __half2 res = __hadd2(mx, __hadd2(e, m1));   // mx + (e - 1)
    return *reinterpret_cast<uint32_t*>(&res);
}

// ---------------- merged prep: X frags (blocks 0..GMT-1) + W blocks (GMT..GMT+FF-1) ----------------
__global__ void prep_kernel(const float* __restrict__ X,
                            const float* __restrict__ W1, const float* __restrict__ W2,
                            const float* __restrict__ b1, const float* __restrict__ b2,
                            const float* __restrict__ W3, const float* __restrict__ b3) {
    if (blockIdx.x < GMT) {
        int gmt = blockIdx.x;
        int t = threadIdx.x;            // 0..319
        int s = t >> 5, lane = t & 31;
        int gid = lane >> 2, tig = lane & 3;
        int r0 = gmt * 16 + gid;
        int c0 = s * 16 + tig * 2;
        float2 v00 = *(const float2*)(X + (size_t)r0 * DD + c0);
        float2 v10 = *(const float2*)(X + (size_t)(r0 + 8) * DD + c0);
        float2 v01 = *(const float2*)(X + (size_t)r0 * DD + c0 + 8);
        float2 v11 = *(const float2*)(X + (size_t)(r0 + 8) * DD + c0 + 8);
        uint4 H;
        H.x = packh2(v00.x, v00.y);
        H.y = packh2(v10.x, v10.y);
        H.z = packh2(v01.x, v01.y);
        H.w = packh2(v11.x, v11.y);
        g_XfragH[((size_t)gmt * KS1 + s) * 32 + lane] = H;
        return;
    }
    int f = blockIdx.x - GMT;
    unsigned char* blk = g_Wblk + (size_t)f * WBLK;
    uint2* w1h = (uint2*)blk;
    uint2* w2h = (uint2*)(blk + 10240);
    float* misc = (float*)(blk + 12288);

    const float* W1f = W1 + (size_t)f * DD * HH;
    for (int i = threadIdx.x; i < KS1 * 4 * 32; i += blockDim.x) {   // 1280, idx = (s*4+nt)*32+lane
        int s = i >> 7, nt = (i >> 5) & 3, lane = i & 31;
        int gid = lane >> 2, tig = lane & 3;
        int n = nt * 8 + gid, k0 = s * 16 + tig * 2;
        float w00 = W1f[k0 * HH + n],       w01 = W1f[(k0 + 1) * HH + n];
        float w10 = W1f[(k0 + 8) * HH + n], w11 = W1f[(k0 + 9) * HH + n];
        w1h[i] = make_uint2(packh2(w00, w01), packh2(w10, w11));
    }
    const float* W2f = W2 + (size_t)f * HH * HH;
    for (int i = threadIdx.x; i < 2 * 4 * 32; i += blockDim.x) {     // 256
        int s = i >> 7, nt = (i >> 5) & 3, lane = i & 31;
        int gid = lane >> 2, tig = lane & 3;
        int n = nt * 8 + gid, k0 = s * 16 + tig * 2;
        float w00 = W2f[k0 * HH + n],       w01 = W2f[(k0 + 1) * HH + n];
        float w10 = W2f[(k0 + 8) * HH + n], w11 = W2f[(k0 + 9) * HH + n];
        w2h[i] = make_uint2(packh2(w00, w01), packh2(w10, w11));
    }
    const float* W3f = W3 + (size_t)f * HH;
    int t = threadIdx.x;
    if (t < HH)            misc[t]      = b1[f * HH + t];
    else if (t < 2 * HH)   misc[t]      = b2[f * HH + (t - HH)];
    else if (t < 3 * HH)   misc[t]      = W3f[t - 2 * HH];
    else if (t == 3 * HH)  misc[96]     = b3[f];
    else if (t >= 104 && t < 120) {
        // fp16 W3 B-fragments, replicated over n: idx = (s3*4+tig)*2 + jj
        int k = t - 104;
        int jj = k & 1, tg = (k >> 1) & 3, s3 = k >> 3;
        int kk = s3 * 16 + jj * 8 + tg * 2;
        ((uint32_t*)misc)[t] = packh2(W3f[kk], W3f[kk + 1]);
    }
    else if (t < 128 && t >= 97) misc[t] = 0.0f;
}

// ---------------- main kernel ----------------
#define SM_W    0                            // NSLOT x WBLK ring
#define SM_MB   (SM_W + NSLOT * WBLK)        // 51200
#define SMEM_DYN (SM_MB + NSLOT * 8)         // 51232

__global__ void __launch_bounds__(NTHR, 3)
mlp_main_kernel(float* __restrict__ out) {
    extern __shared__ unsigned char smem[];
    const uint32_t sb = smem_u32(smem);

    const int tile = blockIdx.x;        // 0..255  (128-row tiles)
    const int f0   = blockIdx.y * NF;   // base network
    const int tid  = threadIdx.x;
    const int wid  = tid >> 5;          // 0..7 -> m-tile within tile
    const int lane = tid & 31;
    const int gid  = lane >> 2, tig = lane & 3;

    if (tid == 0) {
        #pragma unroll
        for (int s = 0; s < NSLOT; s++) MBARRIER_INIT(sb + SM_MB + s * 8, 1);
    }
    __syncthreads();
    if (tid == 0) {
        #pragma unroll
        for (int s = 0; s < NSLOT; s++) {
            MBARRIER_EXPECT_TX(sb + SM_MB + s * 8, (uint32_t)WBLK);
            BULK_G2S(sb + SM_W + s * WBLK,
                     (const void*)(g_Wblk + (size_t)(f0 + s) * WBLK),
                     (uint32_t)WBLK, sb + SM_MB + s * 8);
        }
    }

    // ---- X fragments for this warp's m-tile: registers for all NF f ----
    uint4 xh[KS1];
    {
        const size_t xbase = ((size_t)(tile * 8 + wid) * KS1) * 32 + lane;
        #pragma unroll
        for (int s = 0; s < KS1; s++)
            xh[s] = g_XfragH[xbase + (size_t)s * 32];
    }

    #pragma unroll 1
    for (int j = 0; j < NF; j++) {
        const int slot = j & (NSLOT - 1);
        MBARRIER_WAIT_PARITY(sb + SM_MB + slot * 8, (j >> 2) & 1);
        const unsigned char* wb = smem + SM_W + slot * WBLK;
        const uint2* W1H = (const uint2*)wb;
        const uint2* W2H = (const uint2*)(wb + 10240);
        const float* misc = (const float*)(wb + 12288);

        // ---------- layer 1: fp16(x) @ fp16(W1) ----------
        float acc[4][4];
        #pragma unroll
        for (int nt = 0; nt < 4; nt++) {
            float bc0 = misc[nt * 8 + tig * 2];
            float bc1 = misc[nt * 8 + tig * 2 + 1];
            acc[nt][0] = bc0; acc[nt][1] = bc1;
            acc[nt][2] = bc0; acc[nt][3] = bc1;
        }
        #pragma unroll
        for (int s = 0; s < KS1; s++) {
            uint2 bh0 = W1H[(s * 4 + 0) * 32 + lane];
            uint2 bh1 = W1H[(s * 4 + 1) * 32 + lane];
            uint2 bh2 = W1H[(s * 4 + 2) * 32 + lane];
            uint2 bh3 = W1H[(s * 4 + 3) * 32 + lane];
            mma16816(acc[0], (const uint32_t*)&xh[s], bh0.x, bh0.y);
            mma16816(acc[1], (const uint32_t*)&xh[s], bh1.x, bh1.y);
            mma16816(acc[2], (const uint32_t*)&xh[s], bh2.x, bh2.y);
            mma16816(acc[3], (const uint32_t*)&xh[s], bh3.x, bh3.y);
        }

        // ---------- L1 epilogue: packed fp16 elu -> layer-2 A frags ----------
        uint32_t a2H[2][4];
        #pragma unroll
        for (int nt = 0; nt < 4; nt++) {
            int s2 = nt >> 1, r = (nt & 1) * 2;
            a2H[s2][r + 0] = elu2(acc[nt][0], acc[nt][1]);
            a2H[s2][r + 1] = elu2(acc[nt][2], acc[nt][3]);
        }

        // ---------- layer 2: fp16(h1) @ fp16(W2) ----------
        float acc2[4][4];
        #pragma unroll
        for (int nt = 0; nt < 4; nt++) {
            float bc0 = misc[32 + nt * 8 + tig * 2];
            float bc1 = misc[32 + nt * 8 + tig * 2 + 1];
            acc2[nt][0] = bc0; acc2[nt][1] = bc1;
            acc2[nt][2] = bc0; acc2[nt][3] = bc1;
        }
        #pragma unroll
        for (int s2 = 0; s2 < 2; s2++) {
            uint2 bh0 = W2H[(s2 * 4 + 0) * 32 + lane];
            uint2 bh1 = W2H[(s2 * 4 + 1) * 32 + lane];
            uint2 bh2 = W2H[(s2 * 4 + 2) * 32 + lane];
            uint2 bh3 = W2H[(s2 * 4 + 3) * 32 + lane];
            mma16816(acc2[0], a2H[s2], bh0.x, bh0.y);
            mma16816(acc2[1], a2H[s2], bh1.x, bh1.y);
            mma16816(acc2[2], a2H[s2], bh2.x, bh2.y);
            mma16816(acc2[3], a2H[s2], bh3.x, bh3.y);
        }

        // ---------- layer 3 as 2 MMAs: packed fp16 elu(h2) A frags; W3 fp16 frags
        //            replicated over N (every output col = the dot); C init = b3 ----------
        {
            const uint2* w3f = (const uint2*)(misc + 104);   // idx s3*4 + tig
            uint32_t a3H[2][4];
            #pragma unroll
            for (int nt = 0; nt < 4; nt++) {
                int s3 = nt >> 1, r = (nt & 1) * 2;
                a3H[s3][r + 0] = elu2(acc2[nt][0], acc2[nt][1]);
                a3H[s3][r + 1] = elu2(acc2[nt][2], acc2[nt][3]);
            }
            float b3v = misc[96];
            float c3[4] = {b3v, b3v, b3v, b3v};
            uint2 w0 = w3f[tig];
            uint2 w1 = w3f[4 + tig];
            mma16816(c3, a3H[0], w0.x, w0.y);
            mma16816(c3, a3H[1], w1.x, w1.y);
            if (tig == 0) {
                const int f = f0 + j;
                int row = tile * ROWS + wid * 16 + gid;
                out[(size_t)row * FF + f]       = c3[0];
                out[(size_t)(row + 8) * FF + f] = c3[2];
            }
        }

        __syncthreads();   // all warps done with this W slot
        if (tid == 0 && j + NSLOT < NF) {
            uint32_t mb = sb + SM_MB + slot * 8;
            MBARRIER_EXPECT_TX(mb, (uint32_t)WBLK);
            BULK_G2S(sb + SM_W + slot * WBLK,
                     (const void*)(g_Wblk + (size_t)(f0 + j + NSLOT) * WBLK),
                     (uint32_t)WBLK, mb);
        }
    }
}

// ---------------- launch ----------------
extern "C" void kernel_launch(void* const* d_in, const int* in_sizes, int n_in,
                              void* d_out, int out_size) {
    const float* X  = (const float*)d_in[0];
    const float* W1 = (const float*)d_in[1];
    const float* b1 = (const float*)d_in[2];
    const float* W2 = (const float*)d_in[3];
    const float* b2 = (const float*)d_in[4];
    const float* W3 = (const float*)d_in[5];
    const float* b3 = (const float*)d_in[6];
    float* out = (float*)d_out;

    static int configured = 0;
    if (!configured) {
        cudaFuncSetAttribute(mlp_main_kernel,
                             cudaFuncAttributeMaxDynamicSharedMemorySize, SMEM_DYN);
        configured = 1;
    }

    prep_kernel<<<GMT + FF, 320>>>(X, W1, W2, b1, b2, W3, b3);
    dim3 grid(NN / ROWS, FF / NF);     // (256, 8)
    mlp_main_kernel<<<grid, NTHR, SMEM_DYN>>>(out);
}

// round 14
// speedup vs baseline: 1.6971x; 1.0118x over previous
#include <cuda_runtime.h>
#include <cuda_fp16.h>
#include <cstdint>

// ---------------- problem constants ----------------
#define NN 32768
#define DD 160     // = 10 k-steps of 16
#define FF 128
#define HH 32      // = 4 n-tiles of 8 = 2 k-steps of 16
#define KS1 10     // layer-1 k-steps
#define ROWS 256   // rows per CTA (8 warps x 2 m-tiles)
#define NF 16      // networks per CTA
#define NTHR 256

#define GMT (NN / 16)              // 2048 global m-tiles
#define WBLK 12800                 // per-f weight block bytes (fp16 single W)
#define NSLOT 4                    // W ring depth

// ---------------- device scratch (no allocs) ----------------
__device__ __align__(16) uint4 g_XfragH[(size_t)GMT * KS1 * 32];   // 10.5 MB (fp16)
__device__ __align__(16) unsigned char g_Wblk[(size_t)FF * WBLK];  // 1.6 MB
// per-f block (uint4-paired, 16B/lane conflict-free LDS.128):
//   W1: 10 KB @0     : uint4 index (s*2+h)*32 + lane ; .xy = nt(2h), .zw = nt(2h+1)
//   W2: 2 KB  @10240 : uint4 index (s2*2+h)*32 + lane
//   misc 128 words @12288 : b1[32] | b2[32] | W3[32] | b3 @96 | w3 fp16 frags @104..119

// ---------------- helpers ----------------
__device__ __forceinline__ uint32_t smem_u32(const void* p) {
    uint32_t a;
    asm("{ .reg .u64 t; cvta.to.shared.u64 t, %1; cvt.u32.u64 %0, t; }" : "=r"(a) : "l"(p));
    return a;
}
#define MBARRIER_INIT(addr, cnt) \
    asm volatile("mbarrier.init.shared.b64 [%0], %1;" :: "r"((uint32_t)(addr)), "r"((uint32_t)(cnt)) : "memory")
#define MBARRIER_EXPECT_TX(addr, bytes) \
    asm volatile("mbarrier.arrive.expect_tx.shared.b64 _, [%0], %1;" :: "r"((uint32_t)(addr)), "r"((uint32_t)(bytes)) : "memory")
#define MBARRIER_WAIT_PARITY(mbar_smem_addr, phase_parity) do { \
    uint32_t _mbar = (uint32_t)(mbar_smem_addr); \
    uint32_t _parity = (uint32_t)(phase_parity); \
    uint32_t _done; \
    asm volatile("{\n\t.reg .pred p;\n\t" \
        "mbarrier.try_wait.parity.acquire.cta.shared::cta.b64 p, [%1], %2;\n\t" \
        "selp.b32 %0, 1, 0, p;\n\t}" : "=r"(_done) : "r"(_mbar), "r"(_parity) : "memory"); \
    if (!_done) { \
        asm volatile("{\n\t.reg .pred P1;\n\t" \
            "WAIT_LOOP_%=:\n\t" \
            "mbarrier.try_wait.parity.acquire.cta.shared::cta.b64 P1, [%0], %1, 0x989680;\n\t" \
            "@P1 bra.uni WAIT_DONE_%=;\n\t" \
            "bra.uni WAIT_LOOP_%=;\n\t" \
            "WAIT_DONE_%=:\n\t}" :: "r"(_mbar), "r"(_parity) : "memory"); \
    } \
} while (0)
#define BULK_G2S(dst_smem, src_gmem, bytes, mbar) \
    asm volatile("cp.async.bulk.shared::cluster.global.mbarrier::complete_tx::bytes [%0], [%1], %2, [%3];" \
        :: "r"((uint32_t)(dst_smem)), "l"(src_gmem), "r"((uint32_t)(bytes)), "r"((uint32_t)(mbar)) : "memory")

// mma.m16n8k16 row.col f32.f16.f16.f32 (sm_80+ PTX; no 'a' features)
__device__ __forceinline__ void mma16816(float* c, const uint32_t* a, uint32_t b0, uint32_t b1) {
    asm volatile("mma.sync.aligned.m16n8k16.row.col.f32.f16.f16.f32 "
        "{%0,%1,%2,%3}, {%4,%5,%6,%7}, {%8,%9}, {%0,%1,%2,%3};"
        : "+f"(c[0]), "+f"(c[1]), "+f"(c[2]), "+f"(c[3])
        : "r"(a[0]), "r"(a[1]), "r"(a[2]), "r"(a[3]), "r"(b0), "r"(b1));
}

__device__ __forceinline__ uint32_t packh2(float x, float y) {
    __half2 h = __floats2half2_rn(x, y);
    return *reinterpret_cast<uint32_t*>(&h);
}

// Packed fp16 elu of a pair of fp32 accumulators (R13-proven):
//   elu(x) = max(x,0) + (exp(min(x,0)) - 1), exp via ex2.approx.f16x2.
__device__ __forceinline__ uint32_t elu2(float x, float y) {
    __half2 h = __floats2half2_rn(x, y);
    const __half2 z   = __floats2half2_rn(0.0f, 0.0f);
    const __half2 l2e = __floats2half2_rn(1.4426950408889634f, 1.4426950408889634f);
    const __half2 m1  = __floats2half2_rn(-1.0f, -1.0f);
    __half2 mn = __hmin2(h, z);
    __half2 mx = __hmax2(h, z);
    __half2 t  = __hmul2(mn, l2e);
    uint32_t tu = *reinterpret_cast<uint32_t*>(&t);
    uint32_t eu;
    asm("ex2.approx.f16x2 %0, %1;" : "=r"(eu) : "r"(tu));
    __half2 e = *reinterpret_cast<__half2*>(&eu);
    __half2 res = __hadd2(mx, __hadd2(e, m1));   // mx + (e - 1)
    return *reinterpret_cast<uint32_t*>(&res);
}

// ---------------- merged prep: X frags (blocks 0..GMT-1) + W blocks (GMT..GMT+FF-1) ----------------
__global__ void prep_kernel(const float* __restrict__ X,
                            const float* __restrict__ W1, const float* __restrict__ W2,
                            const float* __restrict__ b1, const float* __restrict__ b2,
                            const float* __restrict__ W3, const float* __restrict__ b3) {
    if (blockIdx.x < GMT) {
        int gmt = blockIdx.x;
        int t = threadIdx.x;            // 0..319
        int s = t >> 5, lane = t & 31;
        int gid = lane >> 2, tig = lane & 3;
        int r0 = gmt * 16 + gid;
        int c0 = s * 16 + tig * 2;
        float2 v00 = *(const float2*)(X + (size_t)r0 * DD + c0);
        float2 v10 = *(const float2*)(X + (size_t)(r0 + 8) * DD + c0);
        float2 v01 = *(const float2*)(X + (size_t)r0 * DD + c0 + 8);
        float2 v11 = *(const float2*)(X + (size_t)(r0 + 8) * DD + c0 + 8);
        uint4 H;
        H.x = packh2(v00.x, v00.y);
        H.y = packh2(v10.x, v10.y);
        H.z = packh2(v01.x, v01.y);
        H.w = packh2(v11.x, v11.y);
        g_XfragH[((size_t)gmt * KS1 + s) * 32 + lane] = H;
        return;
    }
    int f = blockIdx.x - GMT;
    unsigned char* blk = g_Wblk + (size_t)f * WBLK;
    uint2* w1h = (uint2*)blk;
    uint2* w2h = (uint2*)(blk + 10240);
    float* misc = (float*)(blk + 12288);

    const float* W1f = W1 + (size_t)f * DD * HH;
    for (int i = threadIdx.x; i < KS1 * 4 * 32; i += blockDim.x) {   // 1280
        int s = i >> 7, nt = (i >> 5) & 3, lane = i & 31;
        int gid = lane >> 2, tig = lane & 3;
        int n = nt * 8 + gid, k0 = s * 16 + tig * 2;
        float w00 = W1f[k0 * HH + n],       w01 = W1f[(k0 + 1) * HH + n];
        float w10 = W1f[(k0 + 8) * HH + n], w11 = W1f[(k0 + 9) * HH + n];
        // paired uint4 layout: uint2 idx = ((s*2 + nt/2)*32 + lane)*2 + (nt&1)
        w1h[(((s * 2 + (nt >> 1)) * 32 + lane) << 1) + (nt & 1)] =
            make_uint2(packh2(w00, w01), packh2(w10, w11));
    }
    const float* W2f = W2 + (size_t)f * HH * HH;
    for (int i = threadIdx.x; i < 2 * 4 * 32; i += blockDim.x) {     // 256
        int s = i >> 7, nt = (i >> 5) & 3, lane = i & 31;
        int gid = lane >> 2, tig = lane & 3;
        int n = nt * 8 + gid, k0 = s * 16 + tig * 2;
        float w00 = W2f[k0 * HH + n],       w01 = W2f[(k0 + 1) * HH + n];
        float w10 = W2f[(k0 + 8) * HH + n], w11 = W2f[(k0 + 9) * HH + n];
        w2h[(((s * 2 + (nt >> 1)) * 32 + lane) << 1) + (nt & 1)] =
            make_uint2(packh2(w00, w01), packh2(w10, w11));
    }
    const float* W3f = W3 + (size_t)f * HH;
    int t = threadIdx.x;
    if (t < HH)            misc[t]      = b1[f * HH + t];
    else if (t < 2 * HH)   misc[t]      = b2[f * HH + (t - HH)];
    else if (t < 3 * HH)   misc[t]      = W3f[t - 2 * HH];
    else if (t == 3 * HH)  misc[96]     = b3[f];
    else if (t >= 104 && t < 120) {
        // fp16 W3 B-fragments, replicated over n: idx = (s3*4+tig)*2 + jj
        int k = t - 104;
        int jj = k & 1, tg = (k >> 1) & 3, s3 = k >> 3;
        int kk = s3 * 16 + jj * 8 + tg * 2;
        ((uint32_t*)misc)[t] = packh2(W3f[kk], W3f[kk + 1]);
    }
    else if (t < 128 && t >= 97) misc[t] = 0.0f;
}

// ---------------- main kernel ----------------
#define SM_XS   0                            // xh1 stage: 8 warps x 10 s x 32 lanes x 16B = 40960
#define SM_W    40960                        // NSLOT x WBLK ring
#define SM_MB   (SM_W + NSLOT * WBLK)        // 92160
#define SMEM_DYN (SM_MB + NSLOT * 8)         // 92192

__global__ void __launch_bounds__(NTHR, 2)
mlp_main_kernel(float* __restrict__ out) {
    extern __shared__ unsigned char smem[];
    const uint32_t sb = smem_u32(smem);

    const int tile = blockIdx.x;        // 0..127  (256-row tiles)
    const int f0   = blockIdx.y * NF;   // base network
    const int tid  = threadIdx.x;
    const int wid  = tid >> 5;          // 0..7; warp owns m-tiles wid*2, wid*2+1 (of 16)
    const int lane = tid & 31;
    const int gid  = lane >> 2, tig = lane & 3;

    if (tid == 0) {
        #pragma unroll
        for (int s = 0; s < NSLOT; s++) MBARRIER_INIT(sb + SM_MB + s * 8, 1);
    }
    __syncthreads();
    if (tid == 0) {
        #pragma unroll
        for (int s = 0; s < NSLOT; s++) {
            MBARRIER_EXPECT_TX(sb + SM_MB + s * 8, (uint32_t)WBLK);
            BULK_G2S(sb + SM_W + s * WBLK,
                     (const void*)(g_Wblk + (size_t)(f0 + s) * WBLK),
                     (uint32_t)WBLK, sb + SM_MB + s * 8);
        }
    }

    // ---- X fragments: m-tile 0 in registers; m-tile 1 staged to own smem slot
    //      (each thread writes and reads only its own address -> no syncs needed) ----
    uint4 xh0[KS1];
    uint4* xs = (uint4*)(smem + SM_XS) + (wid * KS1) * 32 + lane;
    {
        const size_t xb0 = ((size_t)(tile * 16 + wid * 2 + 0) * KS1) * 32 + lane;
        const size_t xb1 = ((size_t)(tile * 16 + wid * 2 + 1) * KS1) * 32 + lane;
        #pragma unroll
        for (int s = 0; s < KS1; s++) {
            xh0[s] = g_XfragH[xb0 + (size_t)s * 32];
            xs[s * 32] = g_XfragH[xb1 + (size_t)s * 32];
        }
    }

    #pragma unroll 1
    for (int j = 0; j < NF; j++) {
        const int slot = j & (NSLOT - 1);
        MBARRIER_WAIT_PARITY(sb + SM_MB + slot * 8, (j >> 2) & 1);
        const unsigned char* wb = smem + SM_W + slot * WBLK;
        const uint4* W1Q = (const uint4*)wb;
        const uint4* W2Q = (const uint4*)(wb + 10240);
        const float* misc = (const float*)(wb + 12288);

        // ---------- layer 1: fp16(x) @ fp16(W1), both m-tiles share W frags ----------
        float acc[2][4][4];
        #pragma unroll
        for (int nt = 0; nt < 4; nt++) {
            float bc0 = misc[nt * 8 + tig * 2];
            float bc1 = misc[nt * 8 + tig * 2 + 1];
            #pragma unroll
            for (int mt = 0; mt < 2; mt++) {
                acc[mt][nt][0] = bc0; acc[mt][nt][1] = bc1;
                acc[mt][nt][2] = bc0; acc[mt][nt][3] = bc1;
            }
        }
        #pragma unroll
        for (int s = 0; s < KS1; s++) {
            uint4 x1 = xs[s * 32];
            uint4 wA = W1Q[(s * 2 + 0) * 32 + lane];   // nt0 (.xy), nt1 (.zw)
            uint4 wB = W1Q[(s * 2 + 1) * 32 + lane];   // nt2, nt3
            mma16816(acc[0][0], (const uint32_t*)&xh0[s], wA.x, wA.y);
            mma16816(acc[0][1], (const uint32_t*)&xh0[s], wA.z, wA.w);
            mma16816(acc[0][2], (const uint32_t*)&xh0[s], wB.x, wB.y);
            mma16816(acc[0][3], (const uint32_t*)&xh0[s], wB.z, wB.w);
            mma16816(acc[1][0], (const uint32_t*)&x1, wA.x, wA.y);
            mma16816(acc[1][1], (const uint32_t*)&x1, wA.z, wA.w);
            mma16816(acc[1][2], (const uint32_t*)&x1, wB.x, wB.y);
            mma16816(acc[1][3], (const uint32_t*)&x1, wB.z, wB.w);
        }

        // ---------- L1 epilogue: packed fp16 elu -> layer-2 A frags ----------
        uint32_t a2H[2][2][4];
        #pragma unroll
        for (int mt = 0; mt < 2; mt++) {
            #pragma unroll
            for (int nt = 0; nt < 4; nt++) {
                int s2 = nt >> 1, r = (nt & 1) * 2;
                a2H[mt][s2][r + 0] = elu2(acc[mt][nt][0], acc[mt][nt][1]);
                a2H[mt][s2][r + 1] = elu2(acc[mt][nt][2], acc[mt][nt][3]);
            }
        }

        // ---------- layer 2: fp16(h1) @ fp16(W2), shared W frags ----------
        float acc2[2][4][4];
        #pragma unroll
        for (int nt = 0; nt < 4; nt++) {
            float bc0 = misc[32 + nt * 8 + tig * 2];
            float bc1 = misc[32 + nt * 8 + tig * 2 + 1];
            #pragma unroll
            for (int mt = 0; mt < 2; mt++) {
                acc2[mt][nt][0] = bc0; acc2[mt][nt][1] = bc1;
                acc2[mt][nt][2] = bc0; acc2[mt][nt][3] = bc1;
            }
        }
        #pragma unroll
        for (int s2 = 0; s2 < 2; s2++) {
            uint4 wA = W2Q[(s2 * 2 + 0) * 32 + lane];
            uint4 wB = W2Q[(s2 * 2 + 1) * 32 + lane];
            mma16816(acc2[0][0], a2H[0][s2], wA.x, wA.y);
            mma16816(acc2[0][1], a2H[0][s2], wA.z, wA.w);
            mma16816(acc2[0][2], a2H[0][s2], wB.x, wB.y);
            mma16816(acc2[0][3], a2H[0][s2], wB.z, wB.w);
            mma16816(acc2[1][0], a2H[1][s2], wA.x, wA.y);
            mma16816(acc2[1][1], a2H[1][s2], wA.z, wA.w);
            mma16816(acc2[1][2], a2H[1][s2], wB.x, wB.y);
            mma16816(acc2[1][3], a2H[1][s2], wB.z, wB.w);
        }

        // ---------- layer 3 as 2 MMAs per m-tile ----------
        {
            const uint2* w3f = (const uint2*)(misc + 104);   // idx s3*4 + tig
            float b3v = misc[96];
            uint2 w0 = w3f[tig];
            uint2 w1 = w3f[4 + tig];
            const int f = f0 + j;
            #pragma unroll
            for (int mt = 0; mt < 2; mt++) {
                uint32_t a3H[2][4];
                #pragma unroll
                for (int nt = 0; nt < 4; nt++) {
                    int s3 = nt >> 1, r = (nt & 1) * 2;
                    a3H[s3][r + 0] = elu2(acc2[mt][nt][0], acc2[mt][nt][1]);
                    a3H[s3][r + 1] = elu2(acc2[mt][nt][2], acc2[mt][nt][3]);
                }
                float c3[4] = {b3v, b3v, b3v, b3v};
                mma16816(c3, a3H[0], w0.x, w0.y);
                mma16816(c3, a3H[1], w1.x, w1.y);
                if (tig == 0) {
                    int row = tile * ROWS + (wid * 2 + mt) * 16 + gid;
                    out[(size_t)row * FF + f]       = c3[0];
                    out[(size_t)(row + 8) * FF + f] = c3[2];
                }
            }
        }

        __syncthreads();   // all warps done with this W slot
        if (tid == 0 && j + NSLOT < NF) {
            uint32_t mb = sb + SM_MB + slot * 8;
            MBARRIER_EXPECT_TX(mb, (uint32_t)WBLK);
            BULK_G2S(sb + SM_W + slot * WBLK,
                     (const void*)(g_Wblk + (size_t)(f0 + j + NSLOT) * WBLK),
                     (uint32_t)WBLK, mb);
        }
    }
}

// ---------------- launch ----------------
extern "C" void kernel_launch(void* const* d_in, const int* in_sizes, int n_in,
                              void* d_out, int out_size) {
    const float* X  = (const float*)d_in[0];
    const float* W1 = (const float*)d_in[1];
    const float* b1 = (const float*)d_in[2];
    const float* W2 = (const float*)d_in[3];
    const float* b2 = (const float*)d_in[4];
    const float* W3 = (const float*)d_in[5];
    const float* b3 = (const float*)d_in[6];
    float* out = (float*)d_out;

    static int configured = 0;
    if (!configured) {
        cudaFuncSetAttribute(mlp_main_kernel,
                             cudaFuncAttributeMaxDynamicSharedMemorySize, SMEM_DYN);
        configured = 1;
    }

    prep_kernel<<<GMT + FF, 320>>>(X, W1, W2, b1, b2, W3, b3);
    dim3 grid(NN / ROWS, FF / NF);     // (128, 8)
    mlp_main_kernel<<<grid, NTHR, SMEM_DYN>>>(out);
}